// round 1
// baseline (speedup 1.0000x reference)
#include <cuda_runtime.h>

// ---- problem constants ----
#define BSZ 8
#define SEQLEN 16
#define DIM 4096
#define NH 32
#define NKV 8
#define HD 128
#define CACHE 4096
#define M_TOT 128            // BSZ*SEQLEN
#define QKV_N 6144           // 4096 + 1024 + 1024
#define CACHE_PER_B 4194304L // 4096*8*128
#define CK_OFF 524288L
#define CV_OFF 34078720L
#define INV_SQRT_HD 0.08838834764831845f

// ---- scratch ----
__device__ float g_qkv[M_TOT * QKV_N];     // raw projections [m][6144]
__device__ float g_xq[M_TOT * 4096];       // rope'd q [m][h*128+d]
__device__ float g_attn[M_TOT * 4096];     // attn out [m][h*128+d]
__device__ float g_scores[16777216];       // [b][h][q][t]

// ================= cache shift =================
__global__ void shift_caches(const float4* __restrict__ ck,
                             const float4* __restrict__ cv,
                             float4* __restrict__ out) {
    long i = (long)blockIdx.x * 256 + threadIdx.x;
    const long PER = 8L * 4080 * 256;       // float4 per cache
    if (i < PER) {
        long b = i / (4080L * 256), r = i - b * (4080L * 256);
        out[CK_OFF / 4 + b * 1048576 + r] = ck[b * 1048576 + 4096 + r];
    } else if (i < 2 * PER) {
        long j = i - PER;
        long b = j / (4080L * 256), r = j - b * (4080L * 256);
        out[CV_OFF / 4 + b * 1048576 + r] = cv[b * 1048576 + 4096 + r];
    }
}

// ================= QKV projection =================
// C[m][n] = sum_k X[m][k] * W[n][k], tiles 64x64x16, 256 threads, 4x4/thread
__global__ void qkv_gemm(const float* __restrict__ X,
                         const float* __restrict__ wq,
                         const float* __restrict__ wk,
                         const float* __restrict__ wv) {
    __shared__ __align__(16) float As[16 * 68];
    __shared__ __align__(16) float Bs[16 * 68];
    int tid = threadIdx.x;
    int n0 = blockIdx.x * 64, m0 = blockIdx.y * 64;
    const float* W; int nl;
    if (n0 < 4096)      { W = wq; nl = n0; }
    else if (n0 < 5120) { W = wk; nl = n0 - 4096; }
    else                { W = wv; nl = n0 - 5120; }

    int lrow = tid >> 2, lk = (tid & 3) * 4;
    const float* aptr = X + (long)(m0 + lrow) * DIM + lk;
    const float* bptr = W + (long)(nl + lrow) * DIM + lk;
    int trow = (tid >> 4) * 4, tcol = (tid & 15) * 4;
    float acc[16];
#pragma unroll
    for (int i = 0; i < 16; i++) acc[i] = 0.f;

    for (int k0 = 0; k0 < DIM; k0 += 16) {
        float4 av = *(const float4*)(aptr + k0);
        float4 bv = *(const float4*)(bptr + k0);
        As[(lk + 0) * 68 + lrow] = av.x; As[(lk + 1) * 68 + lrow] = av.y;
        As[(lk + 2) * 68 + lrow] = av.z; As[(lk + 3) * 68 + lrow] = av.w;
        Bs[(lk + 0) * 68 + lrow] = bv.x; Bs[(lk + 1) * 68 + lrow] = bv.y;
        Bs[(lk + 2) * 68 + lrow] = bv.z; Bs[(lk + 3) * 68 + lrow] = bv.w;
        __syncthreads();
#pragma unroll
        for (int kk = 0; kk < 16; kk++) {
            float4 a = *(const float4*)&As[kk * 68 + trow];
            float4 b = *(const float4*)&Bs[kk * 68 + tcol];
            acc[0]  += a.x * b.x; acc[1]  += a.x * b.y; acc[2]  += a.x * b.z; acc[3]  += a.x * b.w;
            acc[4]  += a.y * b.x; acc[5]  += a.y * b.y; acc[6]  += a.y * b.z; acc[7]  += a.y * b.w;
            acc[8]  += a.z * b.x; acc[9]  += a.z * b.y; acc[10] += a.z * b.z; acc[11] += a.z * b.w;
            acc[12] += a.w * b.x; acc[13] += a.w * b.y; acc[14] += a.w * b.z; acc[15] += a.w * b.w;
        }
        __syncthreads();
    }
#pragma unroll
    for (int i = 0; i < 4; i++) {
        int m = m0 + trow + i;
#pragma unroll
        for (int j = 0; j < 4; j++)
            g_qkv[(long)m * QKV_N + n0 + tcol + j] = acc[i * 4 + j];
    }
}

// ================= RoPE + scatter new K/V into cache =================
__global__ void rope_scatter(const float* __restrict__ freqs, float* __restrict__ out) {
    int m = blockIdx.x;               // 0..127
    int b = m >> 4, s = m & 15;
    const float* src = g_qkv + (long)m * QKV_N;
    // Q: 2048 (h,i) pairs
    for (int p = threadIdx.x; p < 2048; p += blockDim.x) {
        int i = p & 63;
        float re = src[2 * p], im = src[2 * p + 1];
        float c = freqs[(s * 64 + i) * 2], sn = freqs[(s * 64 + i) * 2 + 1];
        g_xq[(long)m * 4096 + 2 * p]     = re * c - im * sn;
        g_xq[(long)m * 4096 + 2 * p + 1] = re * sn + im * c;
    }
    // K: 512 pairs -> cache tail
    float* ck = out + CK_OFF + (long)b * CACHE_PER_B + (long)(4080 + s) * 1024;
    for (int p = threadIdx.x; p < 512; p += blockDim.x) {
        int i = p & 63;
        float re = src[4096 + 2 * p], im = src[4096 + 2 * p + 1];
        float c = freqs[(s * 64 + i) * 2], sn = freqs[(s * 64 + i) * 2 + 1];
        ck[2 * p]     = re * c - im * sn;
        ck[2 * p + 1] = re * sn + im * c;
    }
    // V: plain copy -> cache tail
    float* cv = out + CV_OFF + (long)b * CACHE_PER_B + (long)(4080 + s) * 1024;
    for (int j = threadIdx.x; j < 1024; j += blockDim.x)
        cv[j] = src[5120 + j];
}

// ================= scores = q @ K^T / sqrt(d) + mask =================
// block: (t-tile 0..63, bkv 0..63); M=64 rows = 4 heads x 16 q
__global__ void scores_gemm(const float* __restrict__ cknew, const float* __restrict__ mask) {
    __shared__ __align__(16) float As[16 * 68];
    __shared__ __align__(16) float Bs[16 * 68];
    int tid = threadIdx.x;
    int t0 = blockIdx.x * 64;
    int b = blockIdx.y >> 3, kv = blockIdx.y & 7;
    int lrow = tid >> 2, lk = (tid & 3) * 4;
    const float* aptr = g_xq + (long)(b * 16 + (lrow & 15)) * 4096 + (kv * 4 + (lrow >> 4)) * 128 + lk;
    const float* bptr = cknew + (long)b * CACHE_PER_B + (long)(t0 + lrow) * 1024 + kv * 128 + lk;
    int trow = (tid >> 4) * 4, tcol = (tid & 15) * 4;
    float acc[16];
#pragma unroll
    for (int i = 0; i < 16; i++) acc[i] = 0.f;

    for (int k0 = 0; k0 < 128; k0 += 16) {
        float4 av = *(const float4*)(aptr + k0);
        float4 bv = *(const float4*)(bptr + k0);
        As[(lk + 0) * 68 + lrow] = av.x; As[(lk + 1) * 68 + lrow] = av.y;
        As[(lk + 2) * 68 + lrow] = av.z; As[(lk + 3) * 68 + lrow] = av.w;
        Bs[(lk + 0) * 68 + lrow] = bv.x; Bs[(lk + 1) * 68 + lrow] = bv.y;
        Bs[(lk + 2) * 68 + lrow] = bv.z; Bs[(lk + 3) * 68 + lrow] = bv.w;
        __syncthreads();
#pragma unroll
        for (int kk = 0; kk < 16; kk++) {
            float4 a = *(const float4*)&As[kk * 68 + trow];
            float4 b2 = *(const float4*)&Bs[kk * 68 + tcol];
            acc[0]  += a.x * b2.x; acc[1]  += a.x * b2.y; acc[2]  += a.x * b2.z; acc[3]  += a.x * b2.w;
            acc[4]  += a.y * b2.x; acc[5]  += a.y * b2.y; acc[6]  += a.y * b2.z; acc[7]  += a.y * b2.w;
            acc[8]  += a.z * b2.x; acc[9]  += a.z * b2.y; acc[10] += a.z * b2.z; acc[11] += a.z * b2.w;
            acc[12] += a.w * b2.x; acc[13] += a.w * b2.y; acc[14] += a.w * b2.z; acc[15] += a.w * b2.w;
        }
        __syncthreads();
    }
#pragma unroll
    for (int i = 0; i < 4; i++) {
        int m = trow + i;
        int h = kv * 4 + (m >> 4), q = m & 15;
        long rowbase = ((long)(b * 32 + h) * 16 + q) * 4096;
#pragma unroll
        for (int j = 0; j < 4; j++) {
            int t = t0 + tcol + j;
            g_scores[rowbase + t] = acc[i * 4 + j] * INV_SQRT_HD + mask[q * 4096 + t];
        }
    }
}

// ================= row softmax over 4096 =================
__global__ void softmax_k() {
    float* row = g_scores + (long)blockIdx.x * 4096;
    int tid = threadIdx.x;
    float v[16];
    float mx = -1e30f;
#pragma unroll
    for (int j = 0; j < 16; j++) {
        v[j] = row[tid + j * 256];
        mx = fmaxf(mx, v[j]);
    }
    __shared__ float red[8];
#pragma unroll
    for (int o = 16; o; o >>= 1) mx = fmaxf(mx, __shfl_xor_sync(0xffffffffu, mx, o));
    if ((tid & 31) == 0) red[tid >> 5] = mx;
    __syncthreads();
    mx = red[0];
#pragma unroll
    for (int i = 1; i < 8; i++) mx = fmaxf(mx, red[i]);
    float s = 0.f;
#pragma unroll
    for (int j = 0; j < 16; j++) { v[j] = __expf(v[j] - mx); s += v[j]; }
#pragma unroll
    for (int o = 16; o; o >>= 1) s += __shfl_xor_sync(0xffffffffu, s, o);
    __syncthreads();
    if ((tid & 31) == 0) red[tid >> 5] = s;
    __syncthreads();
    float tot = 0.f;
#pragma unroll
    for (int i = 0; i < 8; i++) tot += red[i];
    float inv = 1.0f / tot;
#pragma unroll
    for (int j = 0; j < 16; j++) row[tid + j * 256] = v[j] * inv;
}

// ================= attn = probs @ V =================
// block: (n-tile 0..1, bkv 0..63). B is k-major [t][d].
__global__ void attnv_gemm(const float* __restrict__ cvnew) {
    __shared__ __align__(16) float As[16 * 68];
    __shared__ __align__(16) float Bs[16 * 68];
    int tid = threadIdx.x;
    int n0 = blockIdx.x * 64;
    int b = blockIdx.y >> 3, kv = blockIdx.y & 7;
    int lrow = tid >> 2, lk = (tid & 3) * 4;
    const float* aptr = g_scores + ((long)(b * 32 + kv * 4 + (lrow >> 4)) * 16 + (lrow & 15)) * 4096 + lk;
    int bkk = tid >> 4, bn = (tid & 15) * 4;
    const float* bptr = cvnew + (long)b * CACHE_PER_B + (long)bkk * 1024 + kv * 128 + n0 + bn;
    int trow = (tid >> 4) * 4, tcol = (tid & 15) * 4;
    float acc[16];
#pragma unroll
    for (int i = 0; i < 16; i++) acc[i] = 0.f;

    for (int k0 = 0; k0 < 4096; k0 += 16) {
        float4 av = *(const float4*)(aptr + k0);
        float4 bv = *(const float4*)(bptr + (long)k0 * 1024);
        As[(lk + 0) * 68 + lrow] = av.x; As[(lk + 1) * 68 + lrow] = av.y;
        As[(lk + 2) * 68 + lrow] = av.z; As[(lk + 3) * 68 + lrow] = av.w;
        *(float4*)&Bs[bkk * 68 + bn] = bv;
        __syncthreads();
#pragma unroll
        for (int kk = 0; kk < 16; kk++) {
            float4 a = *(const float4*)&As[kk * 68 + trow];
            float4 b2 = *(const float4*)&Bs[kk * 68 + tcol];
            acc[0]  += a.x * b2.x; acc[1]  += a.x * b2.y; acc[2]  += a.x * b2.z; acc[3]  += a.x * b2.w;
            acc[4]  += a.y * b2.x; acc[5]  += a.y * b2.y; acc[6]  += a.y * b2.z; acc[7]  += a.y * b2.w;
            acc[8]  += a.z * b2.x; acc[9]  += a.z * b2.y; acc[10] += a.z * b2.z; acc[11] += a.z * b2.w;
            acc[12] += a.w * b2.x; acc[13] += a.w * b2.y; acc[14] += a.w * b2.z; acc[15] += a.w * b2.w;
        }
        __syncthreads();
    }
#pragma unroll
    for (int i = 0; i < 4; i++) {
        int m = trow + i;
        int h = kv * 4 + (m >> 4), q = m & 15;
#pragma unroll
        for (int j = 0; j < 4; j++) {
            int d = n0 + tcol + j;
            g_attn[(long)(b * 16 + q) * 4096 + h * 128 + d] = acc[i * 4 + j];
        }
    }
}

// ================= out = attn @ wo^T =================
__global__ void out_gemm(const float* __restrict__ wo, float* __restrict__ out) {
    __shared__ __align__(16) float As[16 * 68];
    __shared__ __align__(16) float Bs[16 * 68];
    int tid = threadIdx.x;
    int n0 = blockIdx.x * 64, m0 = blockIdx.y * 64;
    int lrow = tid >> 2, lk = (tid & 3) * 4;
    const float* aptr = g_attn + (long)(m0 + lrow) * 4096 + lk;
    const float* bptr = wo + (long)(n0 + lrow) * 4096 + lk;
    int trow = (tid >> 4) * 4, tcol = (tid & 15) * 4;
    float acc[16];
#pragma unroll
    for (int i = 0; i < 16; i++) acc[i] = 0.f;

    for (int k0 = 0; k0 < 4096; k0 += 16) {
        float4 av = *(const float4*)(aptr + k0);
        float4 bv = *(const float4*)(bptr + k0);
        As[(lk + 0) * 68 + lrow] = av.x; As[(lk + 1) * 68 + lrow] = av.y;
        As[(lk + 2) * 68 + lrow] = av.z; As[(lk + 3) * 68 + lrow] = av.w;
        Bs[(lk + 0) * 68 + lrow] = bv.x; Bs[(lk + 1) * 68 + lrow] = bv.y;
        Bs[(lk + 2) * 68 + lrow] = bv.z; Bs[(lk + 3) * 68 + lrow] = bv.w;
        __syncthreads();
#pragma unroll
        for (int kk = 0; kk < 16; kk++) {
            float4 a = *(const float4*)&As[kk * 68 + trow];
            float4 b2 = *(const float4*)&Bs[kk * 68 + tcol];
            acc[0]  += a.x * b2.x; acc[1]  += a.x * b2.y; acc[2]  += a.x * b2.z; acc[3]  += a.x * b2.w;
            acc[4]  += a.y * b2.x; acc[5]  += a.y * b2.y; acc[6]  += a.y * b2.z; acc[7]  += a.y * b2.w;
            acc[8]  += a.z * b2.x; acc[9]  += a.z * b2.y; acc[10] += a.z * b2.z; acc[11] += a.z * b2.w;
            acc[12] += a.w * b2.x; acc[13] += a.w * b2.y; acc[14] += a.w * b2.z; acc[15] += a.w * b2.w;
        }
        __syncthreads();
    }
#pragma unroll
    for (int i = 0; i < 4; i++) {
        int m = m0 + trow + i;
#pragma unroll
        for (int j = 0; j < 4; j++)
            out[(long)m * 4096 + n0 + tcol + j] = acc[i * 4 + j];
    }
}

// ================= launch =================
extern "C" void kernel_launch(void* const* d_in, const int* in_sizes, int n_in,
                              void* d_out, int out_size) {
    const float* x     = (const float*)d_in[0];
    const float* mask  = (const float*)d_in[1];
    const float* freqs = (const float*)d_in[2];
    const float* ck    = (const float*)d_in[3];
    const float* cv    = (const float*)d_in[4];
    const float* wq    = (const float*)d_in[5];
    const float* wk    = (const float*)d_in[6];
    const float* wv    = (const float*)d_in[7];
    const float* wo    = (const float*)d_in[8];
    float* out = (float*)d_out;

    shift_caches<<<65280, 256>>>((const float4*)ck, (const float4*)cv, (float4*)out);
    qkv_gemm<<<dim3(96, 2), 256>>>(x, wq, wk, wv);
    rope_scatter<<<128, 256>>>(freqs, out);
    scores_gemm<<<dim3(64, 64), 256>>>(out + CK_OFF, mask);
    softmax_k<<<4096, 256>>>();
    attnv_gemm<<<dim3(2, 64), 256>>>(out + CV_OFF);
    out_gemm<<<dim3(64, 2), 256>>>(wo, out);
}

// round 2
// speedup vs baseline: 2.6147x; 2.6147x over previous
#include <cuda_runtime.h>
#include <cstdint>

// ---- problem constants ----
#define BSZ 8
#define SEQLEN 16
#define DIM 4096
#define NH 32
#define NKV 8
#define HD 128
#define CACHE 4096
#define M_TOT 128
#define QKV_N 6144
#define CACHE_PER_B 4194304L // 4096*8*128
#define CK_OFF 524288L
#define CV_OFF 34078720L
#define INV_SQRT_HD 0.08838834764831845f

// ---- scratch ----
__device__ float g_qkv_part[4][M_TOT * QKV_N];   // split-K partials of QKV proj
__device__ float g_xq[8 * 32 * 16 * 128];        // rope'd q, [b][h][q][d]
__device__ float g_scores[4096 * 4096];          // [pair*64 + r][t]
__device__ float g_attn_part[4][64 * 64 * 128];  // split-K partials of probs@V
__device__ float g_attn[M_TOT * 4096];           // [b*16+q][h*128+d]
__device__ float g_out_part[4][M_TOT * DIM];     // split-K partials of out proj

// ---- helpers ----
__device__ __forceinline__ uint32_t f2tf(float f) {
    uint32_t u;
    asm("cvt.rna.tf32.f32 %0, %1;" : "=r"(u) : "f"(f));
    return u;
}

__device__ __forceinline__ void mma_tf32(float (&d)[4], const uint32_t (&a)[4],
                                         const uint32_t (&b)[2]) {
    asm volatile(
        "mma.sync.aligned.m16n8k8.row.col.f32.tf32.tf32.f32 "
        "{%0,%1,%2,%3}, {%4,%5,%6,%7}, {%8,%9}, {%0,%1,%2,%3};\n"
        : "+f"(d[0]), "+f"(d[1]), "+f"(d[2]), "+f"(d[3])
        : "r"(a[0]), "r"(a[1]), "r"(a[2]), "r"(a[3]), "r"(b[0]), "r"(b[1]));
}

// ================= cache shift =================
__global__ void shift_caches(const float4* __restrict__ ck,
                             const float4* __restrict__ cv,
                             float4* __restrict__ out) {
    long i = (long)blockIdx.x * 256 + threadIdx.x;
    const long PER = 8L * 4080 * 256;
    if (i < PER) {
        long b = i / (4080L * 256), r = i - b * (4080L * 256);
        out[CK_OFF / 4 + b * 1048576 + r] = ck[b * 1048576 + 4096 + r];
    } else if (i < 2 * PER) {
        long j = i - PER;
        long b = j / (4080L * 256), r = j - b * (4080L * 256);
        out[CV_OFF / 4 + b * 1048576 + r] = cv[b * 1048576 + 4096 + r];
    }
}

// ================= generic tf32 mma core: C += A(row,[M][K]) * B(row,[N][K])^T ==========
// 256 threads, 8 warps as 2x4; warp tile (MF*16) x 32; BN = 128, BK = 16.
template <int MF>
__device__ __forceinline__ void gemm_abt_core(const float* __restrict__ A, long lda,
                                              const float* __restrict__ B, long ldb,
                                              int ktiles, uint32_t* As, uint32_t* Bs,
                                              float (&acc)[MF][4][4]) {
    const int tid = threadIdx.x;
    const int lane = tid & 31, wid = tid >> 5;
    const int wm = wid >> 2, wn = wid & 3;
    const int g = lane >> 2, tig = lane & 3;

    for (int t = 0; t < ktiles; t++) {
        const float* Ak = A + t * 16;
        const float* Bk = B + t * 16;
#pragma unroll
        for (int i = 0; i < MF / 2; i++) {
            int v = tid + i * 256;
            int r = v >> 2, c4 = v & 3;
            float4 x = *(const float4*)(Ak + (long)r * lda + c4 * 4);
            uint4 y = make_uint4(f2tf(x.x), f2tf(x.y), f2tf(x.z), f2tf(x.w));
            *(uint4*)(As + r * 20 + c4 * 4) = y;
        }
#pragma unroll
        for (int i = 0; i < 2; i++) {
            int v = tid + i * 256;
            int r = v >> 2, c4 = v & 3;
            float4 x = *(const float4*)(Bk + (long)r * ldb + c4 * 4);
            uint4 y = make_uint4(f2tf(x.x), f2tf(x.y), f2tf(x.z), f2tf(x.w));
            *(uint4*)(Bs + r * 20 + c4 * 4) = y;
        }
        __syncthreads();
#pragma unroll
        for (int ks = 0; ks < 16; ks += 8) {
            uint32_t a[MF][4], b[4][2];
#pragma unroll
            for (int mf = 0; mf < MF; mf++) {
                int m = wm * (MF * 16) + mf * 16;
                a[mf][0] = As[(m + g) * 20 + ks + tig];
                a[mf][1] = As[(m + g + 8) * 20 + ks + tig];
                a[mf][2] = As[(m + g) * 20 + ks + tig + 4];
                a[mf][3] = As[(m + g + 8) * 20 + ks + tig + 4];
            }
#pragma unroll
            for (int nf = 0; nf < 4; nf++) {
                int n = wn * 32 + nf * 8 + g;
                b[nf][0] = Bs[n * 20 + ks + tig];
                b[nf][1] = Bs[n * 20 + ks + tig + 4];
            }
#pragma unroll
            for (int mf = 0; mf < MF; mf++)
#pragma unroll
                for (int nf = 0; nf < 4; nf++) mma_tf32(acc[mf][nf], a[mf], b[nf]);
        }
        __syncthreads();
    }
}

template <int MF>
__device__ __forceinline__ void store_acc(float* __restrict__ C, long ldc,
                                          float (&acc)[MF][4][4]) {
    const int tid = threadIdx.x;
    const int lane = tid & 31, wid = tid >> 5;
    const int wm = wid >> 2, wn = wid & 3;
    const int g = lane >> 2, tig = lane & 3;
#pragma unroll
    for (int mf = 0; mf < MF; mf++) {
        int m = wm * (MF * 16) + mf * 16 + g;
#pragma unroll
        for (int nf = 0; nf < 4; nf++) {
            int n = wn * 32 + nf * 8 + 2 * tig;
            *(float2*)(C + (long)m * ldc + n) = make_float2(acc[mf][nf][0], acc[mf][nf][1]);
            *(float2*)(C + (long)(m + 8) * ldc + n) = make_float2(acc[mf][nf][2], acc[mf][nf][3]);
        }
    }
}

// ================= QKV projection (split-K=4) =================
__global__ void qkv_gemm_t(const float* __restrict__ X, const float* __restrict__ wq,
                           const float* __restrict__ wk, const float* __restrict__ wv) {
    __shared__ uint32_t As[128 * 20], Bs[128 * 20];
    int n0 = blockIdx.x * 128, split = blockIdx.y;
    const float* W;
    int nl;
    if (n0 < 4096) { W = wq; nl = n0; }
    else if (n0 < 5120) { W = wk; nl = n0 - 4096; }
    else { W = wv; nl = n0 - 5120; }
    float acc[4][4][4] = {};
    gemm_abt_core<4>(X + split * 1024, 4096, W + (long)nl * 4096 + split * 1024, 4096, 64,
                     As, Bs, acc);
    store_acc<4>(g_qkv_part[split] + n0, QKV_N, acc);
}

// ================= RoPE + split reduce + scatter K/V =================
__global__ void rope_scatter(const float* __restrict__ freqs, float* __restrict__ out) {
    int m = blockIdx.x;  // 0..127
    int b = m >> 4, s = m & 15;
    long base = (long)m * QKV_N;
#pragma unroll 1
    for (int p = threadIdx.x; p < 2048; p += 256) {
        int h = p >> 6, i = p & 63;
        float re = g_qkv_part[0][base + 2 * p] + g_qkv_part[1][base + 2 * p] +
                   g_qkv_part[2][base + 2 * p] + g_qkv_part[3][base + 2 * p];
        float im = g_qkv_part[0][base + 2 * p + 1] + g_qkv_part[1][base + 2 * p + 1] +
                   g_qkv_part[2][base + 2 * p + 1] + g_qkv_part[3][base + 2 * p + 1];
        float c = freqs[(s * 64 + i) * 2], sn = freqs[(s * 64 + i) * 2 + 1];
        long d = ((long)(b * 32 + h) * 16 + s) * 128 + 2 * i;
        g_xq[d] = re * c - im * sn;
        g_xq[d + 1] = re * sn + im * c;
    }
    float* ck = out + CK_OFF + (long)b * CACHE_PER_B + (long)(4080 + s) * 1024;
#pragma unroll 1
    for (int p = threadIdx.x; p < 512; p += 256) {
        int i = p & 63;
        long o = base + 4096 + 2 * p;
        float re = g_qkv_part[0][o] + g_qkv_part[1][o] + g_qkv_part[2][o] + g_qkv_part[3][o];
        float im = g_qkv_part[0][o + 1] + g_qkv_part[1][o + 1] + g_qkv_part[2][o + 1] +
                   g_qkv_part[3][o + 1];
        float c = freqs[(s * 64 + i) * 2], sn = freqs[(s * 64 + i) * 2 + 1];
        ck[2 * p] = re * c - im * sn;
        ck[2 * p + 1] = re * sn + im * c;
    }
    float* cv = out + CV_OFF + (long)b * CACHE_PER_B + (long)(4080 + s) * 1024;
#pragma unroll 1
    for (int j = threadIdx.x; j < 1024; j += 256) {
        long o = base + 5120 + j;
        cv[j] = g_qkv_part[0][o] + g_qkv_part[1][o] + g_qkv_part[2][o] + g_qkv_part[3][o];
    }
}

// ================= scores = q @ K^T * scale + mask =================
__global__ void scores_gemm_t(const float* __restrict__ ck, const float* __restrict__ mask) {
    __shared__ uint32_t As[64 * 20], Bs[128 * 20];
    int t0 = blockIdx.x * 128;
    int pair = blockIdx.y;  // b*8+kv
    int b = pair >> 3, kv = pair & 7;
    float acc[2][4][4] = {};
    const float* A = g_xq + (long)pair * 64 * 128;
    const float* B = ck + (long)b * CACHE_PER_B + (long)t0 * 1024 + kv * 128;
    gemm_abt_core<2>(A, 128, B, 1024, 8, As, Bs, acc);

    const int tid = threadIdx.x;
    const int lane = tid & 31, wid = tid >> 5;
    const int wm = wid >> 2, wn = wid & 3;
    const int g = lane >> 2, tig = lane & 3;
#pragma unroll
    for (int mf = 0; mf < 2; mf++) {
        int m = wm * 32 + mf * 16 + g;
#pragma unroll
        for (int nf = 0; nf < 4; nf++) {
            int n = t0 + wn * 32 + nf * 8 + 2 * tig;
            {
                long row = (long)pair * 64 + m;
                int q = m & 15;
                g_scores[row * 4096 + n] = acc[mf][nf][0] * INV_SQRT_HD + mask[q * 4096 + n];
                g_scores[row * 4096 + n + 1] =
                    acc[mf][nf][1] * INV_SQRT_HD + mask[q * 4096 + n + 1];
            }
            {
                long row = (long)pair * 64 + m + 8;
                int q = (m + 8) & 15;
                g_scores[row * 4096 + n] = acc[mf][nf][2] * INV_SQRT_HD + mask[q * 4096 + n];
                g_scores[row * 4096 + n + 1] =
                    acc[mf][nf][3] * INV_SQRT_HD + mask[q * 4096 + n + 1];
            }
        }
    }
}

// ================= row softmax over 4096 =================
__global__ void softmax_k() {
    float* row = g_scores + (long)blockIdx.x * 4096;
    int tid = threadIdx.x;
    float v[16];
    float mx = -1e30f;
#pragma unroll
    for (int j = 0; j < 16; j++) {
        v[j] = row[tid + j * 256];
        mx = fmaxf(mx, v[j]);
    }
    __shared__ float red[8];
#pragma unroll
    for (int o = 16; o; o >>= 1) mx = fmaxf(mx, __shfl_xor_sync(0xffffffffu, mx, o));
    if ((tid & 31) == 0) red[tid >> 5] = mx;
    __syncthreads();
    mx = red[0];
#pragma unroll
    for (int i = 1; i < 8; i++) mx = fmaxf(mx, red[i]);
    float s = 0.f;
#pragma unroll
    for (int j = 0; j < 16; j++) { v[j] = __expf(v[j] - mx); s += v[j]; }
#pragma unroll
    for (int o = 16; o; o >>= 1) s += __shfl_xor_sync(0xffffffffu, s, o);
    __syncthreads();
    if ((tid & 31) == 0) red[tid >> 5] = s;
    __syncthreads();
    float tot = 0.f;
#pragma unroll
    for (int i = 0; i < 8; i++) tot += red[i];
    float inv = 1.0f / tot;
#pragma unroll
    for (int j = 0; j < 16; j++) row[tid + j * 256] = v[j] * inv;
}

// ================= attn = probs @ V  (split-K=4) =================
// B (V) kept as [k][n] in smem, stride 136 (8k+n covers all banks).
__global__ void attnv_gemm_t(const float* __restrict__ cv) {
    __shared__ uint32_t As[64 * 20], Bs2[16 * 136];
    int pair = blockIdx.x, split = blockIdx.y;
    int b = pair >> 3, kv = pair & 7;
    const float* A = g_scores + (long)pair * 64 * 4096 + split * 1024;
    const float* V = cv + (long)b * CACHE_PER_B + kv * 128 + (long)split * 1024 * 1024;
    float acc[2][4][4] = {};
    const int tid = threadIdx.x;
    const int lane = tid & 31, wid = tid >> 5;
    const int wm = wid >> 2, wn = wid & 3;
    const int g = lane >> 2, tig = lane & 3;

    for (int t = 0; t < 64; t++) {
        {
            int r = tid >> 2, c4 = tid & 3;
            float4 x = *(const float4*)(A + (long)r * 4096 + t * 16 + c4 * 4);
            uint4 y = make_uint4(f2tf(x.x), f2tf(x.y), f2tf(x.z), f2tf(x.w));
            *(uint4*)(As + r * 20 + c4 * 4) = y;
        }
#pragma unroll
        for (int i = 0; i < 2; i++) {
            int v = tid + i * 256;
            int kk = v >> 5, n4 = v & 31;
            float4 x = *(const float4*)(V + (long)(t * 16 + kk) * 1024 + n4 * 4);
            uint4 y = make_uint4(f2tf(x.x), f2tf(x.y), f2tf(x.z), f2tf(x.w));
            *(uint4*)(Bs2 + kk * 136 + n4 * 4) = y;
        }
        __syncthreads();
#pragma unroll
        for (int ks = 0; ks < 16; ks += 8) {
            uint32_t a[2][4], bfr[4][2];
#pragma unroll
            for (int mf = 0; mf < 2; mf++) {
                int m = wm * 32 + mf * 16;
                a[mf][0] = As[(m + g) * 20 + ks + tig];
                a[mf][1] = As[(m + g + 8) * 20 + ks + tig];
                a[mf][2] = As[(m + g) * 20 + ks + tig + 4];
                a[mf][3] = As[(m + g + 8) * 20 + ks + tig + 4];
            }
#pragma unroll
            for (int nf = 0; nf < 4; nf++) {
                int n = wn * 32 + nf * 8 + g;
                bfr[nf][0] = Bs2[(ks + tig) * 136 + n];
                bfr[nf][1] = Bs2[(ks + tig + 4) * 136 + n];
            }
#pragma unroll
            for (int mf = 0; mf < 2; mf++)
#pragma unroll
                for (int nf = 0; nf < 4; nf++) mma_tf32(acc[mf][nf], a[mf], bfr[nf]);
        }
        __syncthreads();
    }
    store_acc<2>(g_attn_part[split] + (long)pair * 64 * 128, 128, acc);
}

__global__ void attnv_reduce() {
    long idx = (long)blockIdx.x * 256 + threadIdx.x;  // float4 index, 131072 total
    long o = idx * 4;
    float4 p0 = ((const float4*)g_attn_part[0])[idx];
    float4 p1 = ((const float4*)g_attn_part[1])[idx];
    float4 p2 = ((const float4*)g_attn_part[2])[idx];
    float4 p3 = ((const float4*)g_attn_part[3])[idx];
    float4 s = make_float4(p0.x + p1.x + p2.x + p3.x, p0.y + p1.y + p2.y + p3.y,
                           p0.z + p1.z + p2.z + p3.z, p0.w + p1.w + p2.w + p3.w);
    int pair = (int)(o >> 13), r = (int)((o >> 7) & 63), d = (int)(o & 127);
    int b = pair >> 3, kv = pair & 7, hp = r >> 4, q = r & 15;
    *(float4*)(g_attn + ((long)(b * 16 + q) * 4096 + (kv * 4 + hp) * 128 + d)) = s;
}

// ================= out = attn @ wo^T (split-K=4) =================
__global__ void out_gemm_t(const float* __restrict__ wo) {
    __shared__ uint32_t As[128 * 20], Bs[128 * 20];
    int n0 = blockIdx.x * 128, split = blockIdx.y;
    float acc[4][4][4] = {};
    gemm_abt_core<4>(g_attn + split * 1024, 4096, wo + (long)n0 * 4096 + split * 1024, 4096,
                     64, As, Bs, acc);
    store_acc<4>(g_out_part[split] + n0, 4096, acc);
}

__global__ void out_reduce(float* __restrict__ out) {
    long idx = (long)blockIdx.x * 256 + threadIdx.x;  // float4 index, 131072 total
    float4 p0 = ((const float4*)g_out_part[0])[idx];
    float4 p1 = ((const float4*)g_out_part[1])[idx];
    float4 p2 = ((const float4*)g_out_part[2])[idx];
    float4 p3 = ((const float4*)g_out_part[3])[idx];
    ((float4*)out)[idx] = make_float4(p0.x + p1.x + p2.x + p3.x, p0.y + p1.y + p2.y + p3.y,
                                      p0.z + p1.z + p2.z + p3.z, p0.w + p1.w + p2.w + p3.w);
}

// ================= launch =================
extern "C" void kernel_launch(void* const* d_in, const int* in_sizes, int n_in,
                              void* d_out, int out_size) {
    const float* x     = (const float*)d_in[0];
    const float* mask  = (const float*)d_in[1];
    const float* freqs = (const float*)d_in[2];
    const float* ck    = (const float*)d_in[3];
    const float* cv    = (const float*)d_in[4];
    const float* wq    = (const float*)d_in[5];
    const float* wk    = (const float*)d_in[6];
    const float* wv    = (const float*)d_in[7];
    const float* wo    = (const float*)d_in[8];
    float* out = (float*)d_out;

    shift_caches<<<65280, 256>>>((const float4*)ck, (const float4*)cv, (float4*)out);
    qkv_gemm_t<<<dim3(48, 4), 256>>>(x, wq, wk, wv);
    rope_scatter<<<128, 256>>>(freqs, out);
    scores_gemm_t<<<dim3(32, 64), 256>>>(out + CK_OFF, mask);
    softmax_k<<<4096, 256>>>();
    attnv_gemm_t<<<dim3(64, 4), 256>>>(out + CV_OFF);
    attnv_reduce<<<512, 256>>>();
    out_gemm_t<<<dim3(32, 4), 256>>>(wo);
    out_reduce<<<512, 256>>>(out);
}